// round 6
// baseline (speedup 1.0000x reference)
#include <cuda_runtime.h>

#define NN 50000
#define EE 800000
#define NEG 0.2f

// ---------------- scratch (device globals) ----------------------------------
__device__ __align__(16) int   g_src[EE];
__device__ __align__(16) int   g_dst[EE];
__device__ __align__(16) int   g_csrc[EE];      // CSR: src ids grouped by dst
__device__ int   g_deg[NN];
__device__ int   g_off[NN + 1];
__device__ int   g_cursor[NN];
__device__ __align__(16) float g_h[NN * 64];
__device__ __align__(16) float g_featA[NN * 64];
__device__ __align__(16) float g_featB[NN * 64];
__device__ __align__(16) float g_as[NN * 4];
__device__ __align__(16) float g_ad[NN * 4];
__device__ int g_is64;

__device__ __forceinline__ float lrelu(float x) { return x > 0.f ? x : NEG * x; }

// ---------------- index prep -------------------------------------------------
__global__ void detect_kernel(const int* __restrict__ ei) {
    if (threadIdx.x == 0) {
        int acc = 0;
        for (int i = 1; i < 128; i += 2) acc |= ei[i];
        g_is64 = (acc == 0) ? 1 : 0;
    }
}

__global__ void convert_hist_kernel(const int* __restrict__ ei) {
    int e = blockIdx.x * blockDim.x + threadIdx.x;
    if (e >= EE) return;
    int s, d;
    if (g_is64) { s = ei[2 * e]; d = ei[2 * (EE + e)]; }
    else        { s = ei[e];     d = ei[EE + e]; }
    g_src[e] = s;
    g_dst[e] = d;
    atomicAdd(&g_deg[d], 1);
}

// single-block exclusive scan of g_deg -> g_off, also seeds g_cursor
__global__ void scan_kernel() {
    __shared__ int part[1024];
    const int CH = (NN + 1023) / 1024;
    int t = threadIdx.x;
    int b0 = t * CH;
    int sum = 0;
    for (int i = 0; i < CH; i++) {
        int idx = b0 + i;
        if (idx < NN) sum += g_deg[idx];
    }
    part[t] = sum;
    __syncthreads();
    for (int off = 1; off < 1024; off <<= 1) {
        int v = (t >= off) ? part[t - off] : 0;
        __syncthreads();
        part[t] += v;
        __syncthreads();
    }
    int run = (t > 0) ? part[t - 1] : 0;
    for (int i = 0; i < CH; i++) {
        int idx = b0 + i;
        if (idx < NN) {
            g_off[idx] = run;
            g_cursor[idx] = run;
            run += g_deg[idx];
        }
    }
    if (t == 1023) g_off[NN] = EE;
}

__global__ void scatter_kernel() {
    int e = blockIdx.x * blockDim.x + threadIdx.x;
    if (e >= EE) return;
    int d = g_dst[e];
    int pos = atomicAdd(&g_cursor[d], 1);
    g_csrc[pos] = g_src[e];
}

// ---------------- fused GEMM + alpha ------------------------------------------
// h = X @ W ; alpha_s / alpha_d. 256 threads, 64-node tile, 4x4 register block.
template <int FIN, int H>
__global__ void gemm_alpha_kernel(const float* __restrict__ X,
                                  const float* __restrict__ W,
                                  const float* __restrict__ As,
                                  const float* __restrict__ Ad) {
    extern __shared__ float smem[];
    float* sW = smem;               // FIN*64
    float* sX = smem + FIN * 64;    // 64*(FIN+1)

    const int tid = threadIdx.x;
    const int node0 = blockIdx.x * 64;

    for (int i = tid; i < FIN * 16; i += 256) {
        float4 v = ((const float4*)W)[i];
        *(float4*)&sW[i * 4] = v;
    }
    const int KV4 = FIN / 4;
    for (int i = tid; i < 64 * KV4; i += 256) {
        int r = i / KV4, c = i % KV4;
        int node = node0 + r;
        float4 v = (node < NN) ? ((const float4*)(X + (size_t)node * FIN))[c]
                               : make_float4(0.f, 0.f, 0.f, 0.f);
        float* row = &sX[r * (FIN + 1)];
        row[c * 4 + 0] = v.x; row[c * 4 + 1] = v.y;
        row[c * 4 + 2] = v.z; row[c * 4 + 3] = v.w;
    }
    __syncthreads();

    const int tx = tid & 15;
    const int ty = tid >> 4;
    float acc[4][4];
#pragma unroll
    for (int i = 0; i < 4; i++)
#pragma unroll
        for (int j = 0; j < 4; j++) acc[i][j] = 0.f;

#pragma unroll 8
    for (int k = 0; k < FIN; k++) {
        float4 w4 = *(const float4*)&sW[k * 64 + tx * 4];
#pragma unroll
        for (int i = 0; i < 4; i++) {
            float xv = sX[(ty * 4 + i) * (FIN + 1) + k];
            acc[i][0] += xv * w4.x;
            acc[i][1] += xv * w4.y;
            acc[i][2] += xv * w4.z;
            acc[i][3] += xv * w4.w;
        }
    }
    __syncthreads();

#pragma unroll
    for (int i = 0; i < 4; i++) {
        int node = node0 + ty * 4 + i;
        if (node < NN) {
            *(float4*)&g_h[node * 64 + tx * 4] =
                make_float4(acc[i][0], acc[i][1], acc[i][2], acc[i][3]);
        }
        float* row = &sX[(ty * 4 + i) * (FIN + 1) + tx * 4];
        row[0] = acc[i][0]; row[1] = acc[i][1];
        row[2] = acc[i][2]; row[3] = acc[i][3];
    }
    __syncthreads();

    if (H == 4) {
        int local = tid >> 2, head = tid & 3;
        int node = node0 + local;
        const float* hrow = &sX[local * (FIN + 1) + head * 16];
        float s = 0.f, d = 0.f;
#pragma unroll
        for (int f = 0; f < 16; f++) {
            float hv = hrow[f];
            s += hv * As[head * 16 + f];
            d += hv * Ad[head * 16 + f];
        }
        if (node < NN) {
            g_as[node * 4 + head] = s;
            g_ad[node * 4 + head] = d;
        }
    } else {
        int local = tid >> 2, q = tid & 3;
        int node = node0 + local;
        const float* hrow = &sX[local * (FIN + 1) + q * 16];
        float s = 0.f, d = 0.f;
#pragma unroll
        for (int f = 0; f < 16; f++) {
            float hv = hrow[f];
            s += hv * As[q * 16 + f];
            d += hv * Ad[q * 16 + f];
        }
        s += __shfl_xor_sync(0xFFFFFFFFu, s, 1);
        s += __shfl_xor_sync(0xFFFFFFFFu, s, 2);
        d += __shfl_xor_sync(0xFFFFFFFFu, d, 1);
        d += __shfl_xor_sync(0xFFFFFFFFu, d, 2);
        if (q == 0 && node < NN) {
            g_as[node] = s;
            g_ad[node] = d;
        }
    }
}

// ---------------- CSR gather: 4 edge-slots x 8 lanes per warp -----------------
// Warp per destination. lane = grp*8 + f; grp = edge slot (4 edges in flight),
// f covers 8 feature cols (2 float4). Self-loop is virtual edge t=0.
// Unshifted softmax (weights are small): w = exp(lrelu(as[s]+ad[d])).
template <int H, bool ELU>
__global__ void gather_kernel(const float* __restrict__ bias,
                              float* __restrict__ out) {
    const unsigned FULL = 0xFFFFFFFFu;
    int d = (blockIdx.x * blockDim.x + threadIdx.x) >> 5;
    if (d >= NN) return;
    const int lane = threadIdx.x & 31;
    const int grp  = lane >> 3;     // edge slot 0..3
    const int f    = lane & 7;      // feature octet 0..7
    const int head = (H == 4) ? (f >> 1) : 0;
    const bool denlane = (H == 4) ? ((f & 1) == 0) : (f == 0);

    const int start = g_off[d];
    const int total = g_off[d + 1] - start + 1;   // +1 self-loop
    const float adv = g_ad[d * H + head];

    float4 a0 = make_float4(0.f, 0.f, 0.f, 0.f);
    float4 a1 = make_float4(0.f, 0.f, 0.f, 0.f);
    float den = 0.f;

    for (int t = grp; t < total; t += 4) {
        int s = (t == 0) ? d : g_csrc[start + t - 1];
        float w = __expf(lrelu(g_as[s * H + head] + adv));
        const float4* hp = (const float4*)&g_h[s * 64 + f * 8];
        float4 h0 = hp[0];
        float4 h1 = hp[1];
        a0.x += w * h0.x; a0.y += w * h0.y; a0.z += w * h0.z; a0.w += w * h0.w;
        a1.x += w * h1.x; a1.y += w * h1.y; a1.z += w * h1.z; a1.w += w * h1.w;
        if (denlane) den += w;
    }

    // reduce across the 4 edge slots (lanes differing in bits 3,4)
#pragma unroll
    for (int off = 8; off <= 16; off <<= 1) {
        a0.x += __shfl_xor_sync(FULL, a0.x, off);
        a0.y += __shfl_xor_sync(FULL, a0.y, off);
        a0.z += __shfl_xor_sync(FULL, a0.z, off);
        a0.w += __shfl_xor_sync(FULL, a0.w, off);
        a1.x += __shfl_xor_sync(FULL, a1.x, off);
        a1.y += __shfl_xor_sync(FULL, a1.y, off);
        a1.z += __shfl_xor_sync(FULL, a1.z, off);
        a1.w += __shfl_xor_sync(FULL, a1.w, off);
        den  += __shfl_xor_sync(FULL, den, off);
    }
    float den_all = (H == 4) ? __shfl_sync(FULL, den, lane & ~1)
                             : __shfl_sync(FULL, den, 0);

    if (grp == 0) {
        float inv = 1.f / (den_all + 1e-16f);
        float4 b0v = ((const float4*)bias)[f * 2 + 0];
        float4 b1v = ((const float4*)bias)[f * 2 + 1];
        float4 v0, v1;
        v0.x = a0.x * inv + b0v.x; v0.y = a0.y * inv + b0v.y;
        v0.z = a0.z * inv + b0v.z; v0.w = a0.w * inv + b0v.w;
        v1.x = a1.x * inv + b1v.x; v1.y = a1.y * inv + b1v.y;
        v1.z = a1.z * inv + b1v.z; v1.w = a1.w * inv + b1v.w;
        if (ELU) {
            v0.x = v0.x > 0.f ? v0.x : expm1f(v0.x);
            v0.y = v0.y > 0.f ? v0.y : expm1f(v0.y);
            v0.z = v0.z > 0.f ? v0.z : expm1f(v0.z);
            v0.w = v0.w > 0.f ? v0.w : expm1f(v0.w);
            v1.x = v1.x > 0.f ? v1.x : expm1f(v1.x);
            v1.y = v1.y > 0.f ? v1.y : expm1f(v1.y);
            v1.z = v1.z > 0.f ? v1.z : expm1f(v1.z);
            v1.w = v1.w > 0.f ? v1.w : expm1f(v1.w);
        }
        float4* op = (float4*)&out[d * 64 + f * 8];
        op[0] = v0;
        op[1] = v1;
    }
}

// ---------------- launch -------------------------------------------------------
extern "C" void kernel_launch(void* const* d_in, const int* in_sizes, int n_in,
                              void* d_out, int out_size) {
    const float* x   = (const float*)d_in[0];
    const int*   ei  = (const int*)d_in[1];
    const float* W0  = (const float*)d_in[2];
    const float* as0 = (const float*)d_in[3];
    const float* ad0 = (const float*)d_in[4];
    const float* b0  = (const float*)d_in[5];
    const float* W1  = (const float*)d_in[6];
    const float* as1 = (const float*)d_in[7];
    const float* ad1 = (const float*)d_in[8];
    const float* b1  = (const float*)d_in[9];
    const float* W2  = (const float*)d_in[10];
    const float* as2 = (const float*)d_in[11];
    const float* ad2 = (const float*)d_in[12];
    const float* b2  = (const float*)d_in[13];
    float* out = (float*)d_out;

    float *featA, *featB;
    void* degp;
    cudaGetSymbolAddress((void**)&featA, g_featA);
    cudaGetSymbolAddress((void**)&featB, g_featB);
    cudaGetSymbolAddress(&degp, g_deg);

    const int smem128 = (128 * 64 + 64 * 129) * 4;   // 65792 B
    const int smem64  = (64 * 64 + 64 * 65) * 4;     // 33024 B
    cudaFuncSetAttribute(gemm_alpha_kernel<128, 4>,
                         cudaFuncAttributeMaxDynamicSharedMemorySize, smem128);
    cudaFuncSetAttribute(gemm_alpha_kernel<64, 4>,
                         cudaFuncAttributeMaxDynamicSharedMemorySize, smem64);
    cudaFuncSetAttribute(gemm_alpha_kernel<64, 1>,
                         cudaFuncAttributeMaxDynamicSharedMemorySize, smem64);

    const int gemm_grid = (NN + 63) / 64;
    const int edge_grid = (EE + 255) / 256;
    const int gath_grid = (NN * 32 + 255) / 256;

    // build CSR
    detect_kernel<<<1, 32>>>(ei);
    cudaMemsetAsync(degp, 0, NN * sizeof(int));
    convert_hist_kernel<<<edge_grid, 256>>>(ei);
    scan_kernel<<<1, 1024>>>();
    scatter_kernel<<<edge_grid, 256>>>();

    // layer 0 : 128 -> 4x16, ELU
    gemm_alpha_kernel<128, 4><<<gemm_grid, 256, smem128>>>(x, W0, as0, ad0);
    gather_kernel<4, true><<<gath_grid, 256>>>(b0, featA);

    // layer 1 : 64 -> 4x16, ELU
    gemm_alpha_kernel<64, 4><<<gemm_grid, 256, smem64>>>(featA, W1, as1, ad1);
    gather_kernel<4, true><<<gath_grid, 256>>>(b1, featB);

    // layer 2 : 64 -> 1x64, no ELU
    gemm_alpha_kernel<64, 1><<<gemm_grid, 256, smem64>>>(featB, W2, as2, ad2);
    gather_kernel<1, false><<<gath_grid, 256>>>(b2, out);
}

// round 7
// speedup vs baseline: 1.0643x; 1.0643x over previous
#include <cuda_runtime.h>

#define NN 50000
#define EE 800000
#define NEG 0.2f

// ---------------- scratch (device globals) ----------------------------------
__device__ __align__(16) int   g_csrc[EE];      // CSR: src ids grouped by dst
__device__ int   g_deg[NN];
__device__ int   g_off[NN + 1];
__device__ int   g_cursor[NN];
__device__ __align__(16) float g_h[NN * 64];
__device__ __align__(16) float g_featA[NN * 64];
__device__ __align__(16) float g_featB[NN * 64];
__device__ __align__(16) float g_as[NN * 4];
__device__ __align__(16) float g_ad[NN * 4];

__device__ __forceinline__ float lrelu(float x) { return x > 0.f ? x : NEG * x; }

// int64 edge_index (values < 2^31): odd 32-bit words of the first lanes are all
// zero. int32: those words are random node ids (P(all zero) ~ 0). Same fixed
// words checked by every thread -> deterministic, L1-broadcast.
__device__ __forceinline__ bool detect64(const int* __restrict__ ei) {
    int acc = 0;
#pragma unroll
    for (int i = 1; i < 16; i += 2) acc |= ei[i];
    return acc == 0;
}

// ---------------- CSR build ---------------------------------------------------
__global__ void hist_kernel(const int* __restrict__ ei) {
    int e = blockIdx.x * blockDim.x + threadIdx.x;
    if (e >= EE) return;
    bool is64 = detect64(ei);
    int d = is64 ? ei[2 * (EE + e)] : ei[EE + e];
    atomicAdd(&g_deg[d], 1);
}

// single-block exclusive scan of g_deg -> g_off, also seeds g_cursor
__global__ void scan_kernel() {
    __shared__ int part[1024];
    const int CH = (NN + 1023) / 1024;
    int t = threadIdx.x;
    int b0 = t * CH;
    int sum = 0;
    for (int i = 0; i < CH; i++) {
        int idx = b0 + i;
        if (idx < NN) sum += g_deg[idx];
    }
    part[t] = sum;
    __syncthreads();
    for (int off = 1; off < 1024; off <<= 1) {
        int v = (t >= off) ? part[t - off] : 0;
        __syncthreads();
        part[t] += v;
        __syncthreads();
    }
    int run = (t > 0) ? part[t - 1] : 0;
    for (int i = 0; i < CH; i++) {
        int idx = b0 + i;
        if (idx < NN) {
            g_off[idx] = run;
            g_cursor[idx] = run;
            run += g_deg[idx];
        }
    }
    if (t == 1023) g_off[NN] = EE;
}

__global__ void scatter_kernel(const int* __restrict__ ei) {
    int e = blockIdx.x * blockDim.x + threadIdx.x;
    if (e >= EE) return;
    bool is64 = detect64(ei);
    int s, d;
    if (is64) { s = ei[2 * e]; d = ei[2 * (EE + e)]; }
    else      { s = ei[e];     d = ei[EE + e]; }
    int pos = atomicAdd(&g_cursor[d], 1);
    g_csrc[pos] = s;
}

// ---------------- fused GEMM + alpha ------------------------------------------
// h = X @ W ; alpha_s / alpha_d. 256 threads, 64-node tile, 4x4 register block.
template <int FIN, int H>
__global__ void gemm_alpha_kernel(const float* __restrict__ X,
                                  const float* __restrict__ W,
                                  const float* __restrict__ As,
                                  const float* __restrict__ Ad) {
    extern __shared__ float smem[];
    float* sW = smem;               // FIN*64
    float* sX = smem + FIN * 64;    // 64*(FIN+1)

    const int tid = threadIdx.x;
    const int node0 = blockIdx.x * 64;

    for (int i = tid; i < FIN * 16; i += 256) {
        float4 v = ((const float4*)W)[i];
        *(float4*)&sW[i * 4] = v;
    }
    const int KV4 = FIN / 4;
    for (int i = tid; i < 64 * KV4; i += 256) {
        int r = i / KV4, c = i % KV4;
        int node = node0 + r;
        float4 v = (node < NN) ? ((const float4*)(X + (size_t)node * FIN))[c]
                               : make_float4(0.f, 0.f, 0.f, 0.f);
        float* row = &sX[r * (FIN + 1)];
        row[c * 4 + 0] = v.x; row[c * 4 + 1] = v.y;
        row[c * 4 + 2] = v.z; row[c * 4 + 3] = v.w;
    }
    __syncthreads();

    const int tx = tid & 15;
    const int ty = tid >> 4;
    float acc[4][4];
#pragma unroll
    for (int i = 0; i < 4; i++)
#pragma unroll
        for (int j = 0; j < 4; j++) acc[i][j] = 0.f;

#pragma unroll 8
    for (int k = 0; k < FIN; k++) {
        float4 w4 = *(const float4*)&sW[k * 64 + tx * 4];
#pragma unroll
        for (int i = 0; i < 4; i++) {
            float xv = sX[(ty * 4 + i) * (FIN + 1) + k];
            acc[i][0] += xv * w4.x;
            acc[i][1] += xv * w4.y;
            acc[i][2] += xv * w4.z;
            acc[i][3] += xv * w4.w;
        }
    }
    __syncthreads();

#pragma unroll
    for (int i = 0; i < 4; i++) {
        int node = node0 + ty * 4 + i;
        if (node < NN) {
            *(float4*)&g_h[node * 64 + tx * 4] =
                make_float4(acc[i][0], acc[i][1], acc[i][2], acc[i][3]);
        }
        float* row = &sX[(ty * 4 + i) * (FIN + 1) + tx * 4];
        row[0] = acc[i][0]; row[1] = acc[i][1];
        row[2] = acc[i][2]; row[3] = acc[i][3];
    }
    __syncthreads();

    if (H == 4) {
        int local = tid >> 2, head = tid & 3;
        int node = node0 + local;
        const float* hrow = &sX[local * (FIN + 1) + head * 16];
        float s = 0.f, d = 0.f;
#pragma unroll
        for (int f = 0; f < 16; f++) {
            float hv = hrow[f];
            s += hv * As[head * 16 + f];
            d += hv * Ad[head * 16 + f];
        }
        if (node < NN) {
            g_as[node * 4 + head] = s;
            g_ad[node * 4 + head] = d;
        }
    } else {
        int local = tid >> 2, q = tid & 3;
        int node = node0 + local;
        const float* hrow = &sX[local * (FIN + 1) + q * 16];
        float s = 0.f, d = 0.f;
#pragma unroll
        for (int f = 0; f < 16; f++) {
            float hv = hrow[f];
            s += hv * As[q * 16 + f];
            d += hv * Ad[q * 16 + f];
        }
        s += __shfl_xor_sync(0xFFFFFFFFu, s, 1);
        s += __shfl_xor_sync(0xFFFFFFFFu, s, 2);
        d += __shfl_xor_sync(0xFFFFFFFFu, d, 1);
        d += __shfl_xor_sync(0xFFFFFFFFu, d, 2);
        if (q == 0 && node < NN) {
            g_as[node] = s;
            g_ad[node] = d;
        }
    }
}

// ---------------- CSR gather: softmax-weighted aggregation, fused epilogue ----
// One warp per destination node. Half-warps process alternating edges.
// Unshifted softmax (weights are small): w = exp(lrelu(as[s]+ad[d])).
template <int H, bool ELU>
__global__ void gather_kernel(const float* __restrict__ bias,
                              float* __restrict__ out) {
    int wg = (blockIdx.x * blockDim.x + threadIdx.x) >> 5;
    if (wg >= NN) return;
    const int lane = threadIdx.x & 31;
    const int half = lane >> 4;
    const int j = lane & 15;
    const int head = (H == 4) ? (j >> 2) : 0;
    const int d = wg;
    const int start = g_off[d];
    const int end   = g_off[d + 1];
    const float adv = g_ad[d * H + head];
    const bool denlane = (H == 4) ? ((j & 3) == 0) : (j == 0);

    float4 acc = make_float4(0.f, 0.f, 0.f, 0.f);
    float den = 0.f;

    if (half == 0) {   // self-loop
        float w = __expf(lrelu(g_as[d * H + head] + adv));
        float4 hv = *(const float4*)&g_h[d * 64 + j * 4];
        acc.x = w * hv.x; acc.y = w * hv.y; acc.z = w * hv.z; acc.w = w * hv.w;
        if (denlane) den = w;
    }

    for (int k = start + half; k < end; k += 2) {
        int s = g_csrc[k];
        float w = __expf(lrelu(g_as[s * H + head] + adv));
        float4 hv = *(const float4*)&g_h[s * 64 + j * 4];
        acc.x += w * hv.x; acc.y += w * hv.y;
        acc.z += w * hv.z; acc.w += w * hv.w;
        if (denlane) den += w;
    }

    acc.x += __shfl_xor_sync(0xFFFFFFFFu, acc.x, 16);
    acc.y += __shfl_xor_sync(0xFFFFFFFFu, acc.y, 16);
    acc.z += __shfl_xor_sync(0xFFFFFFFFu, acc.z, 16);
    acc.w += __shfl_xor_sync(0xFFFFFFFFu, acc.w, 16);
    den   += __shfl_xor_sync(0xFFFFFFFFu, den, 16);
    float den_all = __shfl_sync(0xFFFFFFFFu, den, (H == 4) ? (lane & 12) : 0);

    if (half == 0) {
        float inv = 1.f / (den_all + 1e-16f);
        float4 bv = *(const float4*)&bias[j * 4];
        float4 v;
        v.x = acc.x * inv + bv.x;
        v.y = acc.y * inv + bv.y;
        v.z = acc.z * inv + bv.z;
        v.w = acc.w * inv + bv.w;
        if (ELU) {
            v.x = v.x > 0.f ? v.x : expm1f(v.x);
            v.y = v.y > 0.f ? v.y : expm1f(v.y);
            v.z = v.z > 0.f ? v.z : expm1f(v.z);
            v.w = v.w > 0.f ? v.w : expm1f(v.w);
        }
        *(float4*)&out[d * 64 + j * 4] = v;
    }
}

// ---------------- launch -------------------------------------------------------
extern "C" void kernel_launch(void* const* d_in, const int* in_sizes, int n_in,
                              void* d_out, int out_size) {
    const float* x   = (const float*)d_in[0];
    const int*   ei  = (const int*)d_in[1];
    const float* W0  = (const float*)d_in[2];
    const float* as0 = (const float*)d_in[3];
    const float* ad0 = (const float*)d_in[4];
    const float* b0  = (const float*)d_in[5];
    const float* W1  = (const float*)d_in[6];
    const float* as1 = (const float*)d_in[7];
    const float* ad1 = (const float*)d_in[8];
    const float* b1  = (const float*)d_in[9];
    const float* W2  = (const float*)d_in[10];
    const float* as2 = (const float*)d_in[11];
    const float* ad2 = (const float*)d_in[12];
    const float* b2  = (const float*)d_in[13];
    float* out = (float*)d_out;

    float *featA, *featB;
    void* degp;
    cudaGetSymbolAddress((void**)&featA, g_featA);
    cudaGetSymbolAddress((void**)&featB, g_featB);
    cudaGetSymbolAddress(&degp, g_deg);

    const int smem128 = (128 * 64 + 64 * 129) * 4;   // 65792 B
    const int smem64  = (64 * 64 + 64 * 65) * 4;     // 33024 B
    cudaFuncSetAttribute(gemm_alpha_kernel<128, 4>,
                         cudaFuncAttributeMaxDynamicSharedMemorySize, smem128);
    cudaFuncSetAttribute(gemm_alpha_kernel<64, 4>,
                         cudaFuncAttributeMaxDynamicSharedMemorySize, smem64);
    cudaFuncSetAttribute(gemm_alpha_kernel<64, 1>,
                         cudaFuncAttributeMaxDynamicSharedMemorySize, smem64);

    const int gemm_grid = (NN + 63) / 64;
    const int edge_grid = (EE + 255) / 256;
    const int gath_grid = (NN * 32 + 255) / 256;

    // build CSR   (kernel launches 1..3; gemm128 is #4 -> ncu profiles it)
    cudaMemsetAsync(degp, 0, NN * sizeof(int));
    hist_kernel<<<edge_grid, 256>>>(ei);
    scan_kernel<<<1, 1024>>>();
    scatter_kernel<<<edge_grid, 256>>>(ei);

    // layer 0 : 128 -> 4x16, ELU
    gemm_alpha_kernel<128, 4><<<gemm_grid, 256, smem128>>>(x, W0, as0, ad0);
    gather_kernel<4, true><<<gath_grid, 256>>>(b0, featA);

    // layer 1 : 64 -> 4x16, ELU
    gemm_alpha_kernel<64, 4><<<gemm_grid, 256, smem64>>>(featA, W1, as1, ad1);
    gather_kernel<4, true><<<gath_grid, 256>>>(b1, featB);

    // layer 2 : 64 -> 1x64, no ELU
    gemm_alpha_kernel<64, 1><<<gemm_grid, 256, smem64>>>(featB, W2, as2, ad2);
    gather_kernel<1, false><<<gath_grid, 256>>>(b2, out);
}